// round 1
// baseline (speedup 1.0000x reference)
#include <cuda_runtime.h>
#include <cstdint>

// Problem constants
#define BATCH   4
#define SEQ     8192
#define DIM     512
#define HEADS   8
#define DHEAD   64
#define NTOK    (BATCH * SEQ)          // 32768
#define QKVW    1536
#define SCALE_Q 0.125f                  // 64^-0.5

// ---------------- scratch (device globals: no cudaMalloc allowed) ----------
__device__ float g_h[(size_t)NTOK * DIM];        // LN output, token-major
__device__ float g_qkv[(size_t)NTOK * QKVW];     // qkv
__device__ float g_ctx[BATCH * HEADS * DHEAD * DHEAD];
__device__ float g_qsum[BATCH * DIM];
__device__ float g_o[(size_t)NTOK * DIM];        // attention output pre-projection

// ---------------- init ------------------------------------------------------
__global__ void init_kernel() {
    int i = blockIdx.x * 256 + threadIdx.x;
    if (i < BATCH * HEADS * DHEAD * DHEAD) g_ctx[i] = 0.f;
    if (i < BATCH * DIM) g_qsum[i] = 0.f;
}

// ---------------- LayerNorm + transpose (B,D,N)->(token, D) ----------------
// 32 tokens per block, 256 threads, dyn smem 512*33 floats
__global__ __launch_bounds__(256) void ln_kernel(
    const float* __restrict__ x, const float* __restrict__ lw,
    const float* __restrict__ lb)
{
    extern __shared__ float s[];               // [512][33]
    __shared__ float s_mu[32], s_rs[32];
    int tid = threadIdx.x;
    int token0 = blockIdx.x * 32;
    int b = token0 >> 13;
    int n0 = token0 & (SEQ - 1);
    const float* xb = x + (size_t)b * DIM * SEQ;

    #pragma unroll 4
    for (int i = 0; i < 64; i++) {
        int idx = i * 256 + tid;
        int d = idx >> 5, j = idx & 31;
        s[d * 33 + j] = xb[(size_t)d * SEQ + n0 + j];
    }
    __syncthreads();

    int w = tid >> 5, lane = tid & 31;
    for (int t = 0; t < 4; t++) {
        int j = w * 4 + t;
        float sum = 0.f, sq = 0.f;
        #pragma unroll
        for (int d = lane; d < DIM; d += 32) {
            float v = s[d * 33 + j];
            sum += v; sq += v * v;
        }
        #pragma unroll
        for (int o = 16; o; o >>= 1) {
            sum += __shfl_xor_sync(0xffffffffu, sum, o);
            sq  += __shfl_xor_sync(0xffffffffu, sq, o);
        }
        if (lane == 0) {
            float mu = sum * (1.f / DIM);
            float var = sq * (1.f / DIM) - mu * mu;
            s_mu[j] = mu;
            s_rs[j] = rsqrtf(var + 1e-5f);
        }
    }
    __syncthreads();

    #pragma unroll 4
    for (int i = 0; i < 64; i++) {
        int idx = i * 256 + tid;
        int j = idx >> 9, d = idx & 511;
        g_h[(size_t)(token0 + j) * DIM + d] =
            (s[d * 33 + j] - s_mu[j]) * s_rs[j] * lw[d] + lb[d];
    }
}

// ---------------- SGEMM: C[M,N] = A[M,K] @ W[K,N] ---------------------------
// 128x128 tile, BK=16, 256 threads, 8x8 per thread
__global__ __launch_bounds__(256) void sgemm_kernel(
    const float* __restrict__ A, const float* __restrict__ W,
    float* __restrict__ C, int M, int N, int K)
{
    __shared__ float As[16][128];
    __shared__ float Bs[16][128];
    int tid = threadIdx.x;
    int tx = tid & 15, ty = tid >> 4;
    int row0 = blockIdx.y * 128;
    int col0 = blockIdx.x * 128;

    float acc[8][8] = {};
    int a_r = tid >> 2;                 // 0..63
    int a_c = (tid & 3) * 4;            // 0,4,8,12
    int b_r = tid >> 5;                 // 0..7
    int b_c = (tid & 31) * 4;

    for (int kk = 0; kk < K; kk += 16) {
        #pragma unroll
        for (int sgm = 0; sgm < 2; sgm++) {
            int r = a_r + sgm * 64;
            float4 v = *(const float4*)&A[(size_t)(row0 + r) * K + kk + a_c];
            As[a_c + 0][r] = v.x; As[a_c + 1][r] = v.y;
            As[a_c + 2][r] = v.z; As[a_c + 3][r] = v.w;
        }
        #pragma unroll
        for (int sgm = 0; sgm < 2; sgm++) {
            int r = b_r + sgm * 8;
            *(float4*)&Bs[r][b_c] = *(const float4*)&W[(size_t)(kk + r) * N + col0 + b_c];
        }
        __syncthreads();
        #pragma unroll
        for (int k = 0; k < 16; k++) {
            float af[8], bf[8];
            #pragma unroll
            for (int i = 0; i < 8; i++) af[i] = As[k][ty * 8 + i];
            #pragma unroll
            for (int j = 0; j < 8; j++) bf[j] = Bs[k][tx * 8 + j];
            #pragma unroll
            for (int i = 0; i < 8; i++)
                #pragma unroll
                for (int j = 0; j < 8; j++)
                    acc[i][j] += af[i] * bf[j];
        }
        __syncthreads();
    }
    #pragma unroll
    for (int i = 0; i < 8; i++) {
        size_t r = row0 + ty * 8 + i;
        *(float4*)&C[r * N + col0 + tx * 8 + 0] =
            make_float4(acc[i][0], acc[i][1], acc[i][2], acc[i][3]);
        *(float4*)&C[r * N + col0 + tx * 8 + 4] =
            make_float4(acc[i][4], acc[i][5], acc[i][6], acc[i][7]);
    }
}

// ---------------- k softmax + context accumulation --------------------------
// grid (NTOK/512, HEADS), 256 threads; per-thread 16 fp32 accumulators
__global__ __launch_bounds__(256) void ctx_kernel()
{
    __shared__ float kb[8][64];
    __shared__ float vb[8][64];
    int tid = threadIdx.x;
    int h = blockIdx.y;
    int tok0 = blockIdx.x * 512;
    int b = tok0 >> 13;
    int d = tid & 63, eg = tid >> 6;
    float acc[16] = {};

    for (int t0 = 0; t0 < 512; t0 += 8) {
        #pragma unroll
        for (int sgm = 0; sgm < 2; sgm++) {
            int idx = sgm * 256 + tid;
            int tt = idx >> 6, dd = idx & 63;
            size_t base = (size_t)(tok0 + t0 + tt) * QKVW + h * 64 + dd;
            kb[tt][dd] = g_qkv[base + 512];
            vb[tt][dd] = g_qkv[base + 1024];
        }
        __syncthreads();
        {
            int w = tid >> 5, lane = tid & 31;
            float v0 = kb[w][lane], v1 = kb[w][lane + 32];
            float m = fmaxf(v0, v1);
            #pragma unroll
            for (int o = 16; o; o >>= 1) m = fmaxf(m, __shfl_xor_sync(0xffffffffu, m, o));
            float e0 = __expf(v0 - m), e1 = __expf(v1 - m);
            float su = e0 + e1;
            #pragma unroll
            for (int o = 16; o; o >>= 1) su += __shfl_xor_sync(0xffffffffu, su, o);
            float inv = 1.f / su;
            kb[w][lane] = e0 * inv;
            kb[w][lane + 32] = e1 * inv;
        }
        __syncthreads();
        #pragma unroll
        for (int tt = 0; tt < 8; tt++) {
            float a = kb[tt][d];
            #pragma unroll
            for (int c = 0; c < 16; c++)
                acc[c] += a * vb[tt][eg * 16 + c];
        }
        __syncthreads();
    }
    float* cdst = &g_ctx[((b * HEADS + h) * DHEAD + d) * DHEAD + eg * 16];
    #pragma unroll
    for (int c = 0; c < 16; c++) atomicAdd(&cdst[c], acc[c]);
}

// ---------------- q column sums (sum over tokens of exp(q*scale)) ----------
__global__ __launch_bounds__(512) void qsum_kernel()
{
    int j = threadIdx.x;
    int tok0 = blockIdx.x * 256;
    int b = tok0 >> 13;
    float s = 0.f;
    #pragma unroll 8
    for (int t = 0; t < 256; t++)
        s += __expf(g_qkv[(size_t)(tok0 + t) * QKVW + j] * SCALE_Q);
    atomicAdd(&g_qsum[b * DIM + j], s);
}

// ---------------- o = softmax_n(q) @ ctx per head ---------------------------
// grid (NTOK/64, HEADS), 256 threads
__global__ __launch_bounds__(256) void oproj_kernel()
{
    __shared__ float cs[64][64];
    __shared__ float qt[64][65];
    __shared__ float rq[64];
    int tid = threadIdx.x;
    int h = blockIdx.y;
    int tok0 = blockIdx.x * 64;
    int b = tok0 >> 13;

    const float* csrc = &g_ctx[(b * HEADS + h) * DHEAD * DHEAD];
    for (int i = tid; i < 4096; i += 256) cs[i >> 6][i & 63] = csrc[i];
    if (tid < 64) rq[tid] = 1.f / g_qsum[b * DIM + h * 64 + tid];
    __syncthreads();

    for (int i = tid; i < 64 * 64; i += 256) {
        int t = i >> 6, dd = i & 63;
        float qv = g_qkv[(size_t)(tok0 + t) * QKVW + h * 64 + dd];
        qt[t][dd] = __expf(qv * SCALE_Q) * rq[dd];
    }
    __syncthreads();

    int tx = tid & 15, ty = tid >> 4;
    float acc[4][4] = {};
    #pragma unroll
    for (int dd = 0; dd < 64; dd++) {
        float a[4], bb[4];
        #pragma unroll
        for (int i = 0; i < 4; i++) a[i] = qt[ty * 4 + i][dd];
        #pragma unroll
        for (int j = 0; j < 4; j++) bb[j] = cs[dd][tx * 4 + j];
        #pragma unroll
        for (int i = 0; i < 4; i++)
            #pragma unroll
            for (int j = 0; j < 4; j++)
                acc[i][j] += a[i] * bb[j];
    }
    #pragma unroll
    for (int i = 0; i < 4; i++) {
        *(float4*)&g_o[(size_t)(tok0 + ty * 4 + i) * DIM + h * 64 + tx * 4] =
            make_float4(acc[i][0], acc[i][1], acc[i][2], acc[i][3]);
    }
}

// ---------------- final GEMM with bias + transposed store -------------------
// out[b, dout, n] = sum_j o[token, j] * w_out[j, dout] + b_out[dout]
__global__ __launch_bounds__(256) void gemm_out_kernel(
    const float* __restrict__ W, const float* __restrict__ bias,
    float* __restrict__ out)
{
    extern __shared__ float sm[];
    float (*As)[128] = (float(*)[128])sm;
    float (*Bs)[128] = (float(*)[128])(sm + 16 * 128);
    float* st = sm;                             // reused after mainloop: [128][132]

    const int Nn = 512, K = 512;
    int tid = threadIdx.x;
    int tx = tid & 15, ty = tid >> 4;
    int row0 = blockIdx.y * 128;                // token tile
    int col0 = blockIdx.x * 128;                // dout tile

    float acc[8][8] = {};
    int a_r = tid >> 2;
    int a_c = (tid & 3) * 4;
    int b_r = tid >> 5;
    int b_c = (tid & 31) * 4;

    for (int kk = 0; kk < K; kk += 16) {
        #pragma unroll
        for (int sgm = 0; sgm < 2; sgm++) {
            int r = a_r + sgm * 64;
            float4 v = *(const float4*)&g_o[(size_t)(row0 + r) * K + kk + a_c];
            As[a_c + 0][r] = v.x; As[a_c + 1][r] = v.y;
            As[a_c + 2][r] = v.z; As[a_c + 3][r] = v.w;
        }
        #pragma unroll
        for (int sgm = 0; sgm < 2; sgm++) {
            int r = b_r + sgm * 8;
            *(float4*)&Bs[r][b_c] = *(const float4*)&W[(size_t)(kk + r) * Nn + col0 + b_c];
        }
        __syncthreads();
        #pragma unroll
        for (int k = 0; k < 16; k++) {
            float af[8], bf[8];
            #pragma unroll
            for (int i = 0; i < 8; i++) af[i] = As[k][ty * 8 + i];
            #pragma unroll
            for (int j = 0; j < 8; j++) bf[j] = Bs[k][tx * 8 + j];
            #pragma unroll
            for (int i = 0; i < 8; i++)
                #pragma unroll
                for (int j = 0; j < 8; j++)
                    acc[i][j] += af[i] * bf[j];
        }
        __syncthreads();
    }

    // stage to smem [token][dout] then write transposed, coalesced over tokens
    #pragma unroll
    for (int i = 0; i < 8; i++) {
        *(float4*)&st[(ty * 8 + i) * 132 + tx * 8 + 0] =
            make_float4(acc[i][0], acc[i][1], acc[i][2], acc[i][3]);
        *(float4*)&st[(ty * 8 + i) * 132 + tx * 8 + 4] =
            make_float4(acc[i][4], acc[i][5], acc[i][6], acc[i][7]);
    }
    __syncthreads();

    int b = row0 >> 13;
    int n0 = row0 & (SEQ - 1);
    for (int idx = tid; idx < 128 * 128; idx += 256) {
        int r = idx >> 7;     // dout offset
        int c = idx & 127;    // token offset
        out[(size_t)b * DIM * SEQ + (size_t)(col0 + r) * SEQ + n0 + c] =
            st[c * 132 + r] + bias[col0 + r];
    }
}

// ---------------- launch ----------------------------------------------------
extern "C" void kernel_launch(void* const* d_in, const int* in_sizes, int n_in,
                              void* d_out, int out_size)
{
    const float* x     = (const float*)d_in[0];
    const float* ln_w  = (const float*)d_in[1];
    const float* ln_b  = (const float*)d_in[2];
    const float* w_qkv = (const float*)d_in[3];
    const float* w_out = (const float*)d_in[4];
    const float* b_out = (const float*)d_in[5];
    float* out = (float*)d_out;

    float *p_h, *p_qkv;
    cudaGetSymbolAddress((void**)&p_h, g_h);
    cudaGetSymbolAddress((void**)&p_qkv, g_qkv);

    const int LN_SMEM  = 512 * 33 * 4;     // 67584 B
    const int OUT_SMEM = 128 * 132 * 4;    // 67584 B
    cudaFuncSetAttribute(ln_kernel, cudaFuncAttributeMaxDynamicSharedMemorySize, LN_SMEM);
    cudaFuncSetAttribute(gemm_out_kernel, cudaFuncAttributeMaxDynamicSharedMemorySize, OUT_SMEM);

    // 1. zero accumulators
    init_kernel<<<(BATCH * HEADS * DHEAD * DHEAD + 255) / 256, 256>>>();
    // 2. LayerNorm + transpose
    ln_kernel<<<NTOK / 32, 256, LN_SMEM>>>(x, ln_w, ln_b);
    // 3. QKV GEMM: (32768 x 512) @ (512 x 1536)
    sgemm_kernel<<<dim3(QKVW / 128, NTOK / 128), 256>>>(p_h, w_qkv, p_qkv, NTOK, QKVW, DIM);
    // 4. k-softmax + context
    ctx_kernel<<<dim3(NTOK / 512, HEADS), 256>>>();
    // 5. q column sums
    qsum_kernel<<<NTOK / 256, 512>>>();
    // 6. o = softmax(q) @ ctx
    oproj_kernel<<<dim3(NTOK / 64, HEADS), 256>>>();
    // 7. output GEMM + bias + transpose
    gemm_out_kernel<<<dim3(DIM / 128, NTOK / 128), 256, OUT_SMEM>>>(w_out, b_out, out);
}

// round 3
// speedup vs baseline: 2.0545x; 2.0545x over previous
#include <cuda_runtime.h>
#include <cuda_bf16.h>
#include <cstdint>

#define BATCH   4
#define SEQ     8192
#define DIM     512
#define HEADS   8
#define NTOK    32768
#define QKVW    1536
#define SCALE_Q 0.125f
#define MTILES  256
#define PADT    133

// ---------------- scratch ----------------
__device__ __align__(16) __nv_bfloat16 g_ah[(size_t)NTOK * DIM];
__device__ __align__(16) __nv_bfloat16 g_al[(size_t)NTOK * DIM];
__device__ __align__(16) __nv_bfloat16 g_oh[(size_t)NTOK * DIM];
__device__ __align__(16) __nv_bfloat16 g_ol[(size_t)NTOK * DIM];
__device__ __align__(16) __nv_bfloat16 g_wqh[(size_t)DIM * QKVW];
__device__ __align__(16) __nv_bfloat16 g_wql[(size_t)DIM * QKVW];
__device__ __align__(16) __nv_bfloat16 g_woh[(size_t)DIM * DIM];
__device__ __align__(16) __nv_bfloat16 g_wol[(size_t)DIM * DIM];
__device__ float g_qkv[(size_t)NTOK * QKVW];
__device__ float g_ctx[BATCH * HEADS * 64 * 64];
__device__ float g_qsum[BATCH * DIM];

// ---------------- PTX helpers (non-arch-specific only) ----------------
__device__ __forceinline__ uint32_t s2u(const void* p) {
    uint32_t a;
    asm("{ .reg .u64 t; cvta.to.shared.u64 t, %1; cvt.u32.u64 %0, t; }" : "=r"(a) : "l"(p));
    return a;
}
#define CP16(d, s)                                                            \
    asm volatile("cp.async.cg.shared.global [%0], [%1], 16;" :: "r"(d), "l"(s) : "memory")
#define CPCOMMIT() asm volatile("cp.async.commit_group;" ::: "memory")
#define CPWAIT1()  asm volatile("cp.async.wait_group 1;" ::: "memory")
#define LDSM_X4(r, a)                                                         \
    asm volatile("ldmatrix.sync.aligned.m8n8.x4.shared.b16 {%0,%1,%2,%3}, [%4];" \
        : "=r"((r)[0]), "=r"((r)[1]), "=r"((r)[2]), "=r"((r)[3]) : "r"(a))
#define LDSM_X2T(r, a)                                                        \
    asm volatile("ldmatrix.sync.aligned.m8n8.x2.trans.shared.b16 {%0,%1}, [%2];" \
        : "=r"((r)[0]), "=r"((r)[1]) : "r"(a))
#define MMA(d, a, b)                                                          \
    asm volatile("mma.sync.aligned.m16n8k16.row.col.f32.bf16.bf16.f32 "       \
        "{%0,%1,%2,%3},{%4,%5,%6,%7},{%8,%9},{%0,%1,%2,%3};"                  \
        : "+f"((d)[0]), "+f"((d)[1]), "+f"((d)[2]), "+f"((d)[3])              \
        : "r"((a)[0]), "r"((a)[1]), "r"((a)[2]), "r"((a)[3]),                 \
          "r"((b)[0]), "r"((b)[1]))

// ---------------- init ----------------
__global__ void init_kernel() {
    int i = blockIdx.x * 256 + threadIdx.x;
    if (i < BATCH * HEADS * 64 * 64) g_ctx[i] = 0.f;
    if (i < BATCH * DIM) g_qsum[i] = 0.f;
}

// ---------------- LayerNorm + transpose -> row-major bf16 hi/lo ------------
__global__ __launch_bounds__(256) void ln_kernel(
    const float* __restrict__ x, const float* __restrict__ lw,
    const float* __restrict__ lb)
{
    extern __shared__ float s[];               // [512][33]
    __shared__ float s_mu[32], s_rs[32];
    int tid = threadIdx.x;
    int token0 = blockIdx.x * 32;
    int b = token0 >> 13;
    int n0 = token0 & (SEQ - 1);
    const float* xb = x + (size_t)b * DIM * SEQ;

    #pragma unroll 4
    for (int i = 0; i < 64; i++) {
        int idx = i * 256 + tid;
        int d = idx >> 5, j = idx & 31;
        s[d * 33 + j] = xb[(size_t)d * SEQ + n0 + j];
    }
    __syncthreads();

    int w = tid >> 5, lane = tid & 31;
    for (int t = 0; t < 4; t++) {
        int j = w * 4 + t;
        float sum = 0.f, sq = 0.f;
        #pragma unroll
        for (int d = lane; d < DIM; d += 32) {
            float v = s[d * 33 + j];
            sum += v; sq += v * v;
        }
        #pragma unroll
        for (int o = 16; o; o >>= 1) {
            sum += __shfl_xor_sync(0xffffffffu, sum, o);
            sq  += __shfl_xor_sync(0xffffffffu, sq, o);
        }
        if (lane == 0) {
            float mu = sum * (1.f / DIM);
            float var = sq * (1.f / DIM) - mu * mu;
            s_mu[j] = mu;
            s_rs[j] = rsqrtf(var + 1e-5f);
        }
    }
    __syncthreads();

    #pragma unroll
    for (int it = 0; it < 8; it++) {
        int idx = it * 256 + tid;              // 2048 = 32 tokens x 64 groups of 8
        int g = idx & 63, j = idx >> 6;
        int d0 = g * 8;
        float mu = s_mu[j], rs = s_rs[j];
        union { __nv_bfloat16 h[8]; uint4 u; } ph, pl;
        #pragma unroll
        for (int i = 0; i < 8; i++) {
            int d = d0 + i;
            float v = (s[d * 33 + j] - mu) * rs * lw[d] + lb[d];
            __nv_bfloat16 hv = __float2bfloat16(v);
            ph.h[i] = hv;
            pl.h[i] = __float2bfloat16(v - __bfloat162float(hv));
        }
        size_t off = (size_t)(token0 + j) * DIM + d0;
        *(uint4*)&g_ah[off] = ph.u;
        *(uint4*)&g_al[off] = pl.u;
    }
}

// ---------------- weight fp32 -> bf16 hi/lo ---------------------------------
__global__ __launch_bounds__(256) void wconv_kernel(
    const float* __restrict__ wq, const float* __restrict__ wo)
{
    int stride = gridDim.x * 256;
    for (int i = blockIdx.x * 256 + threadIdx.x; i < DIM * QKVW; i += stride) {
        float v = wq[i];
        __nv_bfloat16 h = __float2bfloat16(v);
        g_wqh[i] = h;
        g_wql[i] = __float2bfloat16(v - __bfloat162float(h));
    }
    for (int i = blockIdx.x * 256 + threadIdx.x; i < DIM * DIM; i += stride) {
        float v = wo[i];
        __nv_bfloat16 h = __float2bfloat16(v);
        g_woh[i] = h;
        g_wol[i] = __float2bfloat16(v - __bfloat162float(h));
    }
}

// ---------------- split-bf16 HMMA GEMM: C = A @ B, K=512 --------------------
// A row-major [32768,512] (hi,lo), B row-major [512,ldb] (hi,lo).
// mode 0: C[token][ldb] fp32. mode 1: out[b][dout][n] + bias (transposed store).
#define STAGE 20992
__global__ __launch_bounds__(256) void mma_gemm_kernel(
    const __nv_bfloat16* __restrict__ Ah, const __nv_bfloat16* __restrict__ Al,
    const __nv_bfloat16* __restrict__ Bh, const __nv_bfloat16* __restrict__ Bl,
    float* __restrict__ C, const float* __restrict__ bias, int ldb, int mode)
{
    extern __shared__ char smem[];
    uint32_t sb = s2u(smem);
    int tid = threadIdx.x, lane = tid & 31, wid = tid >> 5;
    int m0 = blockIdx.y * 128, n0 = blockIdx.x * 128;
    int wm = (wid >> 2) * 64, wn = (wid & 3) * 32;

    // cp.async source/dest for this thread
    int ar = tid >> 1, ah8 = (tid & 1) * 8;         // A: row, k-half
    int bkr = tid >> 4, bn8 = (tid & 15) * 8;       // B: k-row, n-offset
    const __nv_bfloat16* Agh = Ah + (size_t)(m0 + ar) * DIM + ah8;
    const __nv_bfloat16* Agl = Al + (size_t)(m0 + ar) * DIM + ah8;
    const __nv_bfloat16* Bgh = Bh + (size_t)bkr * ldb + n0 + bn8;
    const __nv_bfloat16* Bgl = Bl + (size_t)bkr * ldb + n0 + bn8;
    uint32_t dAh = sb + ar * 48 + ah8 * 2;
    uint32_t dAl = dAh + 6144;
    uint32_t dBh = sb + 12288 + bkr * 272 + bn8 * 2;
    uint32_t dBl = dBh + 4352;

    // ldmatrix base addresses (within stage 0)
    uint32_t aAddr[4], bAddr[4];
    #pragma unroll
    for (int mi = 0; mi < 4; mi++)
        aAddr[mi] = sb + (wm + mi * 16 + (lane & 15)) * 48 + (lane >> 4) * 16;
    #pragma unroll
    for (int ni = 0; ni < 4; ni++)
        bAddr[ni] = sb + 12288 + (lane & 15) * 272 + (wn + ni * 8) * 2;

    float d[4][4][4];
    #pragma unroll
    for (int mi = 0; mi < 4; mi++)
        #pragma unroll
        for (int ni = 0; ni < 4; ni++)
            #pragma unroll
            for (int r = 0; r < 4; r++) d[mi][ni][r] = 0.f;

    // prologue: stages 0,1
    #pragma unroll
    for (int p = 0; p < 2; p++) {
        uint32_t so = p * STAGE;
        CP16(dAh + so, Agh + p * 16);
        CP16(dAl + so, Agl + p * 16);
        CP16(dBh + so, Bgh + (size_t)p * 16 * ldb);
        CP16(dBl + so, Bgl + (size_t)p * 16 * ldb);
        CPCOMMIT();
    }

    for (int kk = 0; kk < 32; kk++) {
        CPWAIT1();
        __syncthreads();
        if (kk + 2 < 32) {
            uint32_t so = ((kk + 2) % 3) * STAGE;
            CP16(dAh + so, Agh + (kk + 2) * 16);
            CP16(dAl + so, Agl + (kk + 2) * 16);
            CP16(dBh + so, Bgh + (size_t)(kk + 2) * 16 * ldb);
            CP16(dBl + so, Bgl + (size_t)(kk + 2) * 16 * ldb);
        }
        CPCOMMIT();

        uint32_t so = (kk % 3) * STAGE;
        uint32_t ah[4][4], al[4][4], bh[4][2], bl[4][2];
        #pragma unroll
        for (int mi = 0; mi < 4; mi++) {
            LDSM_X4(ah[mi], aAddr[mi] + so);
            LDSM_X4(al[mi], aAddr[mi] + so + 6144);
        }
        #pragma unroll
        for (int ni = 0; ni < 4; ni++) {
            LDSM_X2T(bh[ni], bAddr[ni] + so);
            LDSM_X2T(bl[ni], bAddr[ni] + so + 4352);
        }
        #pragma unroll
        for (int mi = 0; mi < 4; mi++)
            #pragma unroll
            for (int ni = 0; ni < 4; ni++) {
                MMA(d[mi][ni], ah[mi], bh[ni]);
                MMA(d[mi][ni], ah[mi], bl[ni]);
                MMA(d[mi][ni], al[mi], bh[ni]);
            }
    }

    if (mode == 0) {
        // direct fp32 stores (16B-chunk coalescing via float2 per thread)
        #pragma unroll
        for (int mi = 0; mi < 4; mi++) {
            int r0 = m0 + wm + mi * 16 + (lane >> 2);
            #pragma unroll
            for (int ni = 0; ni < 4; ni++) {
                int c0 = n0 + wn + ni * 8 + (lane & 3) * 2;
                *(float2*)&C[(size_t)r0 * ldb + c0] =
                    make_float2(d[mi][ni][0], d[mi][ni][1]);
                *(float2*)&C[(size_t)(r0 + 8) * ldb + c0] =
                    make_float2(d[mi][ni][2], d[mi][ni][3]);
            }
        }
    } else {
        // stage to smem, transposed store with bias
        __syncthreads();
        float* st = (float*)smem;             // [128][PADT]
        #pragma unroll
        for (int mi = 0; mi < 4; mi++) {
            int r0 = wm + mi * 16 + (lane >> 2);
            #pragma unroll
            for (int ni = 0; ni < 4; ni++) {
                int c0 = wn + ni * 8 + (lane & 3) * 2;
                st[r0 * PADT + c0]       = d[mi][ni][0];
                st[r0 * PADT + c0 + 1]   = d[mi][ni][1];
                st[(r0 + 8) * PADT + c0]     = d[mi][ni][2];
                st[(r0 + 8) * PADT + c0 + 1] = d[mi][ni][3];
            }
        }
        __syncthreads();
        int b = m0 >> 13, nn0 = m0 & (SEQ - 1);
        float* dst = C + (size_t)b * DIM * SEQ + (size_t)n0 * SEQ + nn0;
        for (int idx = tid; idx < 16384; idx += 256) {
            int r = idx >> 7;     // dout offset within tile
            int c = idx & 127;    // token offset
            dst[(size_t)r * SEQ + c] = st[c * PADT + r] + bias[n0 + r];
        }
    }
}

// ---------------- k softmax + context accumulation --------------------------
__global__ __launch_bounds__(256) void ctx_kernel()
{
    __shared__ float kb[16][64];
    __shared__ float vb[16][64];
    int tid = threadIdx.x;
    int h = blockIdx.y;
    int tok0 = blockIdx.x * 512;
    int b = tok0 >> 13;
    int d = tid & 63, eg = tid >> 6;
    int ltt = tid >> 4, ld4 = (tid & 15) * 4;
    float acc[16] = {};

    for (int t0 = 0; t0 < 512; t0 += 16) {
        size_t base = (size_t)(tok0 + t0 + ltt) * QKVW + h * 64 + ld4;
        *(float4*)&kb[ltt][ld4] = *(const float4*)&g_qkv[base + 512];
        *(float4*)&vb[ltt][ld4] = *(const float4*)&g_qkv[base + 1024];
        __syncthreads();
        {
            int w = tid >> 5, lane = tid & 31;
            #pragma unroll
            for (int u = 0; u < 2; u++) {
                int tt = w * 2 + u;
                float e0 = __expf(kb[tt][lane]);
                float e1 = __expf(kb[tt][lane + 32]);
                float su = e0 + e1;
                #pragma unroll
                for (int o = 16; o; o >>= 1) su += __shfl_xor_sync(0xffffffffu, su, o);
                float inv = 1.f / su;
                kb[tt][lane] = e0 * inv;
                kb[tt][lane + 32] = e1 * inv;
            }
        }
        __syncthreads();
        #pragma unroll
        for (int tt = 0; tt < 16; tt++) {
            float a = kb[tt][d];
            #pragma unroll
            for (int c = 0; c < 16; c++)
                acc[c] += a * vb[tt][eg * 16 + c];
        }
        __syncthreads();
    }
    float* cdst = &g_ctx[((b * HEADS + h) * 64 + d) * 64 + eg * 16];
    #pragma unroll
    for (int c = 0; c < 16; c++) atomicAdd(&cdst[c], acc[c]);
}

// ---------------- q column sums ----------------------------------------------
__global__ __launch_bounds__(512) void qsum_kernel()
{
    int j = threadIdx.x;
    int tok0 = blockIdx.x * 256;
    int b = tok0 >> 13;
    float s = 0.f;
    #pragma unroll 8
    for (int t = 0; t < 256; t++)
        s += __expf(g_qkv[(size_t)(tok0 + t) * QKVW + j] * SCALE_Q);
    atomicAdd(&g_qsum[b * DIM + j], s);
}

// ---------------- o = softmax_n(q) @ ctx ; write row-major hi/lo ------------
__global__ __launch_bounds__(256) void oproj_kernel()
{
    __shared__ float cs[64][64];
    __shared__ float qt[64][65];
    __shared__ float rq[64];
    int tid = threadIdx.x;
    int h = blockIdx.y;
    int tok0 = blockIdx.x * 64;
    int b = tok0 >> 13;

    const float* csrc = &g_ctx[(b * HEADS + h) * 64 * 64];
    for (int i = tid; i < 4096; i += 256) cs[i >> 6][i & 63] = csrc[i];
    if (tid < 64) rq[tid] = 1.f / g_qsum[b * DIM + h * 64 + tid];
    __syncthreads();

    for (int i = tid; i < 64 * 64; i += 256) {
        int t = i >> 6, dd = i & 63;
        float qv = g_qkv[(size_t)(tok0 + t) * QKVW + h * 64 + dd];
        qt[t][dd] = __expf(qv * SCALE_Q) * rq[dd];
    }
    __syncthreads();

    int tx = tid & 15, ty = tid >> 4;
    float acc[4][4] = {};
    #pragma unroll
    for (int dd = 0; dd < 64; dd++) {
        float a[4], bb[4];
        #pragma unroll
        for (int i = 0; i < 4; i++) a[i] = qt[ty * 4 + i][dd];
        #pragma unroll
        for (int j = 0; j < 4; j++) bb[j] = cs[dd][tx * 4 + j];
        #pragma unroll
        for (int i = 0; i < 4; i++)
            #pragma unroll
            for (int j = 0; j < 4; j++)
                acc[i][j] += a[i] * bb[j];
    }
    #pragma unroll
    for (int i = 0; i < 4; i++) {
        int t = tok0 + ty * 4 + i;
        union { __nv_bfloat16 h2[4]; uint2 u; } ph, pl;
        #pragma unroll
        for (int j = 0; j < 4; j++) {
            __nv_bfloat16 hv = __float2bfloat16(acc[i][j]);
            ph.h2[j] = hv;
            pl.h2[j] = __float2bfloat16(acc[i][j] - __bfloat162float(hv));
        }
        size_t off = (size_t)t * DIM + h * 64 + tx * 4;
        *(uint2*)&g_oh[off] = ph.u;
        *(uint2*)&g_ol[off] = pl.u;
    }
}

// ---------------- launch ------------------------------------------------------
extern "C" void kernel_launch(void* const* d_in, const int* in_sizes, int n_in,
                              void* d_out, int out_size)
{
    const float* x     = (const float*)d_in[0];
    const float* ln_w  = (const float*)d_in[1];
    const float* ln_b  = (const float*)d_in[2];
    const float* w_qkv = (const float*)d_in[3];
    const float* w_out = (const float*)d_in[4];
    const float* b_out = (const float*)d_in[5];
    float* out = (float*)d_out;

    __nv_bfloat16 *p_ah, *p_al, *p_oh, *p_ol, *p_wqh, *p_wql, *p_woh, *p_wol;
    float* p_qkv;
    cudaGetSymbolAddress((void**)&p_ah, g_ah);
    cudaGetSymbolAddress((void**)&p_al, g_al);
    cudaGetSymbolAddress((void**)&p_oh, g_oh);
    cudaGetSymbolAddress((void**)&p_ol, g_ol);
    cudaGetSymbolAddress((void**)&p_wqh, g_wqh);
    cudaGetSymbolAddress((void**)&p_wql, g_wql);
    cudaGetSymbolAddress((void**)&p_woh, g_woh);
    cudaGetSymbolAddress((void**)&p_wol, g_wol);
    cudaGetSymbolAddress((void**)&p_qkv, g_qkv);

    const int LN_SMEM   = 512 * 33 * 4;
    const int GEMM_SMEM = 128 * PADT * 4;    // 68096 > 3*STAGE = 62976
    cudaFuncSetAttribute(ln_kernel, cudaFuncAttributeMaxDynamicSharedMemorySize, LN_SMEM);
    cudaFuncSetAttribute(mma_gemm_kernel, cudaFuncAttributeMaxDynamicSharedMemorySize, GEMM_SMEM);

    init_kernel<<<(BATCH * HEADS * 64 * 64 + 255) / 256, 256>>>();
    ln_kernel<<<NTOK / 32, 256, LN_SMEM>>>(x, ln_w, ln_b);
    wconv_kernel<<<1024, 256>>>(w_qkv, w_out);
    // QKV GEMM (tensor cores via mma.sync, split bf16)
    mma_gemm_kernel<<<dim3(QKVW / 128, MTILES), 256, GEMM_SMEM>>>(
        p_ah, p_al, p_wqh, p_wql, p_qkv, nullptr, QKVW, 0);
    ctx_kernel<<<dim3(NTOK / 512, HEADS), 256>>>();
    qsum_kernel<<<NTOK / 256, 512>>>();
    oproj_kernel<<<dim3(NTOK / 64, HEADS), 256>>>();
    // output GEMM (+bias, transposed store)
    mma_gemm_kernel<<<dim3(DIM / 128, MTILES), 256, GEMM_SMEM>>>(
        p_oh, p_ol, p_woh, p_wol, out, b_out, DIM, 1);
}